// round 1
// baseline (speedup 1.0000x reference)
#include <cuda_runtime.h>
#include <math.h>

#define NTOT 1024
#define NI   64
#define NO   64
#define NC   960          // kept columns: j = 64..1023  (j' = j-64)
#define WARM 25

// ---------------- device scratch (no runtime allocation allowed) ----------
__device__ __align__(16) float g_S[NTOT * NC];   // S[k][j'] = sig_diff[k][64+j']   (3.93 MB)
__device__ __align__(16) float g_ST[NC * NC];    // ST[j'][k'] = S[64+k'][64+j']    (3.69 MB)
__device__ __align__(16) float g_ctop[NC];       // sum_{k<64} S[k][j']
__device__ __align__(16) float g_reg[2][NC];     // unnormalized reg, ping-pong
__device__ __align__(16) float g_sv[WARM + 2];   // s_i chain (g_sv[0]=1)
__device__ __align__(16) float g_base[NC];       // batch-constant offset

// ---------------- init ----------------------------------------------------
__global__ void k_init() {
    int t = blockIdx.x * blockDim.x + threadIdx.x;
    if (t < NC) g_reg[0][t] = 1.0f / (float)NTOT;
    if (t < WARM + 2) g_sv[t] = (t == 0) ? 1.0f : 0.0f;
}

// ---------------- signature matrix ----------------------------------------
__global__ void k_sig(const float* __restrict__ ident, const float* __restrict__ enh,
                      const float* __restrict__ inh, const float* __restrict__ beta) {
    int t = blockIdx.x * blockDim.x + threadIdx.x;
    if (t >= NTOT * NC) return;
    int k = t / NC, jp = t % NC;
    float v = 0.0f;
    if (k < NI || k >= NI + NO) {            // rows 64..127 masked to 0
        float b   = beta[0];
        float idj = ident[jp + NI];
        v = expf(-b * fabsf(enh[k] - idj)) - expf(-b * fabsf(inh[k] - idj));
    }
    g_S[k * NC + jp] = v;
    if (k >= NI) g_ST[jp * NC + (k - NI)] = v;   // transposed copy for warmup dots
}

__global__ void k_colsum() {
    int j = blockIdx.x * blockDim.x + threadIdx.x;
    if (j >= NC) return;
    float s = 0.0f;
    #pragma unroll 8
    for (int k = 0; k < NI; k++) s += g_S[k * NC + j];
    g_ctop[j] = s;
}

// ---------------- one warmup iteration ------------------------------------
// conc[j] = reg_prev[j]/s ; dc[j] = (d/N)*( (1/N)*ctop[j] + (1/s)*dot(reg_prev, ST[j]) )
// reg_new[j] = max(conc[j]+dc[j], 0) ; s_new = sum(reg_new)  (via atomics)
__global__ void k_iter(int it, const float* __restrict__ delta) {
    __shared__ float sreg[NC];
    int p = it & 1;
    for (int t = threadIdx.x; t < NC; t += blockDim.x) sreg[t] = g_reg[p][t];
    __syncthreads();
    float s   = g_sv[it];
    float inv = (s > 0.0f) ? 1.0f / s : 1.0f;
    float d   = delta[0];
    int warp = threadIdx.x >> 5, lane = threadIdx.x & 31;
    int j = blockIdx.x * 8 + warp;              // 120 blocks * 8 warps = 960
    if (j >= NC) return;
    float acc = 0.0f;
    const float* row = g_ST + j * NC;
    for (int k = lane; k < NC; k += 32) acc = fmaf(sreg[k], row[k], acc);
    #pragma unroll
    for (int o = 16; o; o >>= 1) acc += __shfl_xor_sync(0xffffffffu, acc, o);
    if (lane == 0) {
        float dc = (d / (float)NTOT) * ((1.0f / (float)NTOT) * g_ctop[j] + inv * acc);
        float nv = fmaxf(sreg[j] * inv + dc, 0.0f);
        g_reg[p ^ 1][j] = nv;
        atomicAdd(&g_sv[it + 1], nv);
    }
}

// ---------------- batch-constant base vector -------------------------------
// base[j] = warm[j] + (d/N)*(1/s25)*dot(reg25, ST[j])
__global__ void k_base(const float* __restrict__ delta) {
    __shared__ float sreg[NC];
    int p = WARM & 1;
    for (int t = threadIdx.x; t < NC; t += blockDim.x) sreg[t] = g_reg[p][t];
    __syncthreads();
    float s   = g_sv[WARM];
    float inv = (s > 0.0f) ? 1.0f / s : 1.0f;
    float d   = delta[0];
    int warp = threadIdx.x >> 5, lane = threadIdx.x & 31;
    int j = blockIdx.x * 8 + warp;
    if (j >= NC) return;
    float acc = 0.0f;
    const float* row = g_ST + j * NC;
    for (int k = lane; k < NC; k += 32) acc = fmaf(sreg[k], row[k], acc);
    #pragma unroll
    for (int o = 16; o; o >>= 1) acc += __shfl_xor_sync(0xffffffffu, acc, o);
    if (lane == 0) g_base[j] = sreg[j] * inv + (d / (float)NTOT) * inv * acc;
}

// ---------------- fused batch GEMM + relu + rowsum + normalize -------------
// v[b][j'] = max(base[j'] + (d/N)*dot(x_b, S[0:64][j']), 0)
// out[b][c] = v[b][c] / sum_{j'} v[b][j']   (c = 0..63, i.e. global cols 64..127)
#define SMEM_FLOATS (8192 + 4096 + 2048 + 128)   // sA + sW + sRS + sInv
__global__ void __launch_bounds__(256) k_gemm(const float* __restrict__ X,
                                              const float* __restrict__ delta,
                                              float* __restrict__ out) {
    extern __shared__ float sm[];
    float* sA   = sm;            // 128 x 64
    float* sW   = sm + 8192;     // 64 x 64
    float* sRS  = sm + 12288;    // 128 x 16
    float* sInv = sm + 14336;    // 128
    int tid = threadIdx.x;
    int r0  = blockIdx.x * 128;

    // load A tile (128 rows x 64 cols) as float4
    #pragma unroll
    for (int t = 0; t < 8; t++) {
        int f = t * 256 + tid;   // 2048 float4 total
        ((float4*)sA)[f] = ((const float4*)(X + (size_t)r0 * 64))[f];
    }

    int ty = tid >> 4, tx = tid & 15;  // thread -> rows ty*8+i, cols tx*4+c
    float d  = delta[0];
    float sc = d / (float)NTOT;
    float rs[8];
    #pragma unroll
    for (int i = 0; i < 8; i++) rs[i] = 0.0f;
    float vout[8][4];

    __syncthreads();
    for (int cc = 0; cc < 15; cc++) {
        // load W chunk (64 x 64) from g_S
        #pragma unroll
        for (int t = 0; t < 4; t++) {
            int f = t * 256 + tid;             // 1024 float4
            int k = f >> 4, c4 = f & 15;
            ((float4*)sW)[f] = *(const float4*)(g_S + k * NC + cc * 64 + c4 * 4);
        }
        __syncthreads();

        float acc[8][4];
        #pragma unroll
        for (int i = 0; i < 8; i++)
            #pragma unroll
            for (int c = 0; c < 4; c++) acc[i][c] = 0.0f;

        #pragma unroll
        for (int k = 0; k < 64; k += 4) {
            float4 a4[8];
            #pragma unroll
            for (int i = 0; i < 8; i++)
                a4[i] = *(const float4*)(sA + (ty * 8 + i) * 64 + k);
            #pragma unroll
            for (int kk = 0; kk < 4; kk++) {
                float4 b4 = *(const float4*)(sW + (k + kk) * 64 + tx * 4);
                #pragma unroll
                for (int i = 0; i < 8; i++) {
                    float av = (kk == 0) ? a4[i].x : (kk == 1) ? a4[i].y
                             : (kk == 2) ? a4[i].z : a4[i].w;
                    acc[i][0] = fmaf(av, b4.x, acc[i][0]);
                    acc[i][1] = fmaf(av, b4.y, acc[i][1]);
                    acc[i][2] = fmaf(av, b4.z, acc[i][2]);
                    acc[i][3] = fmaf(av, b4.w, acc[i][3]);
                }
            }
        }

        // per-chunk epilogue: add base, relu, accumulate row sums; keep chunk0
        float bb[4];
        #pragma unroll
        for (int c = 0; c < 4; c++) bb[c] = g_base[cc * 64 + tx * 4 + c];
        #pragma unroll
        for (int i = 0; i < 8; i++) {
            #pragma unroll
            for (int c = 0; c < 4; c++) {
                float v = fmaxf(bb[c] + sc * acc[i][c], 0.0f);
                rs[i] += v;
                if (cc == 0) vout[i][c] = v;
            }
        }
        __syncthreads();
    }

    // row-sum reduction across the 16 column-threads
    #pragma unroll
    for (int i = 0; i < 8; i++) sRS[(ty * 8 + i) * 16 + tx] = rs[i];
    __syncthreads();
    if (tid < 128) {
        float s = 0.0f;
        #pragma unroll
        for (int x = 0; x < 16; x++) s += sRS[tid * 16 + x];
        sInv[tid] = (s > 0.0f) ? 1.0f / s : 1.0f;
    }
    __syncthreads();

    // write out normalized cols 0..63
    #pragma unroll
    for (int i = 0; i < 8; i++) {
        int row = ty * 8 + i;
        float iv = sInv[row];
        float4 o = make_float4(vout[i][0] * iv, vout[i][1] * iv,
                               vout[i][2] * iv, vout[i][3] * iv);
        *(float4*)(out + (size_t)(r0 + row) * 64 + tx * 4) = o;
    }
}

// ---------------- launch ----------------------------------------------------
extern "C" void kernel_launch(void* const* d_in, const int* in_sizes, int n_in,
                              void* d_out, int out_size) {
    const float* inputs      = (const float*)d_in[0];
    const float* identifiers = (const float*)d_in[1];
    const float* enhancers   = (const float*)d_in[2];
    const float* inhibitors  = (const float*)d_in[3];
    const float* beta        = (const float*)d_in[4];
    const float* delta       = (const float*)d_in[5];
    (void)in_sizes; (void)n_in; (void)out_size;

    cudaFuncSetAttribute(k_gemm, cudaFuncAttributeMaxDynamicSharedMemorySize,
                         SMEM_FLOATS * (int)sizeof(float));

    k_init<<<4, 256>>>();
    k_sig<<<(NTOT * NC + 255) / 256, 256>>>(identifiers, enhancers, inhibitors, beta);
    k_colsum<<<(NC + 255) / 256, 256>>>();
    for (int i = 0; i < WARM; i++) k_iter<<<120, 256>>>(i, delta);
    k_base<<<120, 256>>>(delta);
    k_gemm<<<128, 256, SMEM_FLOATS * (int)sizeof(float)>>>(inputs, delta, (float*)d_out);
}

// round 2
// speedup vs baseline: 1.0320x; 1.0320x over previous
#include <cuda_runtime.h>
#include <math.h>

#define NTOT 1024
#define NI   64
#define NO   64
#define NC   960
#define WARM 25
#define GRID 128
#define TPB  256

typedef unsigned long long u64;

// ---------------- device scratch ----------------
__device__ __align__(16) float g_S[NTOT * NC];   // S[k][j']   (j' = j-64)
__device__ __align__(16) float g_ST[NC * NC];    // ST[j'][k'] = S[64+k'][64+j']
__device__ __align__(16) float g_ctop[NC];
__device__ __align__(16) float g_reg[2][NC];
__device__ __align__(16) float g_sv[WARM + 2];
__device__ __align__(16) float g_base[NC];
__device__ unsigned g_bar[32];

// ---------------- init (separate launch: resets barrier counters) ----------
__global__ void k_init() {
    int t = blockIdx.x * blockDim.x + threadIdx.x;
    if (t < NC) g_reg[0][t] = 1.0f / (float)NTOT;
    if (t < WARM + 2) g_sv[t] = (t == 0) ? 1.0f : 0.0f;
    if (t < 32) g_bar[t] = 0u;
}

// ---------------- global barrier (all GRID blocks co-resident) -------------
__device__ __forceinline__ void gbar(int id) {
    __syncthreads();
    __threadfence();
    if (threadIdx.x == 0) {
        atomicAdd(&g_bar[id], 1u);
        unsigned v;
        do {
            asm volatile("ld.acquire.gpu.u32 %0, [%1];"
                         : "=r"(v) : "l"(&g_bar[id]) : "memory");
        } while (v < (unsigned)GRID);
    }
    __syncthreads();
}

// ---------------- packed f32x2 helpers ----------------
__device__ __forceinline__ u64 pack_dup(float x) {
    u64 d;
    asm("mov.b64 %0, {%1, %1};" : "=l"(d) : "f"(x));
    return d;
}
__device__ __forceinline__ void fma2(u64& d, u64 a, u64 b) {
    asm("fma.rn.f32x2 %0, %1, %2, %0;" : "+l"(d) : "l"(a), "l"(b));
}
__device__ __forceinline__ void unpack2(u64 a, float& lo, float& hi) {
    asm("mov.b64 {%0, %1}, %2;" : "=f"(lo), "=f"(hi) : "l"(a));
}

// smem plan (floats):
//   sAT : 64 x 128 (A transposed, k-major)          [0, 8192)
//   sW  : 64 x 64  (W chunk)                        [8192, 12288)
//   sRS : 128 x 16                                  [12288, 14336)
//   sInv: 128                                       [14336, 14464)
//   (warmup reuses [0, 960) as sreg)
#define SMEM_FLOATS 14464

__global__ void __launch_bounds__(TPB, 1)
k_fused(const float* __restrict__ X,
        const float* __restrict__ ident, const float* __restrict__ enh,
        const float* __restrict__ inh,  const float* __restrict__ beta,
        const float* __restrict__ delta, float* __restrict__ out) {
    extern __shared__ float sm[];
    float* sreg = sm;
    float* sAT  = sm;
    float* sW   = sm + 8192;
    float* sRS  = sm + 12288;
    float* sInv = sm + 14336;

    const int tid  = threadIdx.x;
    const int bx   = blockIdx.x;
    const int warp = tid >> 5, lane = tid & 31;
    const float d  = delta[0];

    // ===== phase 1: signature matrix =====
    {
        const float b = beta[0];
        for (int t = bx * TPB + tid; t < NTOT * NC; t += GRID * TPB) {
            int k = t / NC, jp = t - k * NC;
            float v = 0.0f;
            if (k < NI || k >= NI + NO) {
                float idj = ident[jp + NI];
                v = expf(-b * fabsf(enh[k] - idj)) - expf(-b * fabsf(inh[k] - idj));
            }
            g_S[k * NC + jp] = v;
            if (k >= NI) g_ST[jp * NC + (k - NI)] = v;
        }
    }
    gbar(0);

    // ===== phase 2: column sums over top 64 rows =====
    {
        int j = bx * TPB + tid;
        if (j < NC) {
            float s = 0.0f;
            #pragma unroll 8
            for (int k = 0; k < NI; k++) s += g_S[k * NC + j];
            g_ctop[j] = s;
        }
    }
    gbar(1);

    // ===== phase 3: warmup iterations (sequential, grid-wide) =====
    const int j = bx * 8 + warp;   // blocks 0..119 cover j = 0..959
    for (int it = 0; it < WARM; it++) {
        int p = it & 1;
        if (tid < 240) ((float4*)sreg)[tid] = ((const float4*)g_reg[p])[tid];
        __syncthreads();
        if (j < NC) {
            float s   = g_sv[it];
            float inv = (s > 0.0f) ? 1.0f / s : 1.0f;
            float acc = 0.0f;
            const float4* row4 = (const float4*)(g_ST + j * NC);
            for (int v = lane; v < 240; v += 32) {
                float4 a = ((const float4*)sreg)[v];
                float4 w = row4[v];
                acc = fmaf(a.x, w.x, acc); acc = fmaf(a.y, w.y, acc);
                acc = fmaf(a.z, w.z, acc); acc = fmaf(a.w, w.w, acc);
            }
            #pragma unroll
            for (int o = 16; o; o >>= 1) acc += __shfl_xor_sync(0xffffffffu, acc, o);
            if (lane == 0) {
                float dc = (d / (float)NTOT) *
                           ((1.0f / (float)NTOT) * g_ctop[j] + inv * acc);
                float nv = fmaxf(sreg[j] * inv + dc, 0.0f);
                g_reg[p ^ 1][j] = nv;
                atomicAdd(&g_sv[it + 1], nv);
            }
        }
        gbar(2 + it);
    }

    // ===== phase 4: batch-constant base vector =====
    {
        int p = WARM & 1;
        if (tid < 240) ((float4*)sreg)[tid] = ((const float4*)g_reg[p])[tid];
        __syncthreads();
        if (j < NC) {
            float s   = g_sv[WARM];
            float inv = (s > 0.0f) ? 1.0f / s : 1.0f;
            float acc = 0.0f;
            const float4* row4 = (const float4*)(g_ST + j * NC);
            for (int v = lane; v < 240; v += 32) {
                float4 a = ((const float4*)sreg)[v];
                float4 w = row4[v];
                acc = fmaf(a.x, w.x, acc); acc = fmaf(a.y, w.y, acc);
                acc = fmaf(a.z, w.z, acc); acc = fmaf(a.w, w.w, acc);
            }
            #pragma unroll
            for (int o = 16; o; o >>= 1) acc += __shfl_xor_sync(0xffffffffu, acc, o);
            if (lane == 0)
                g_base[j] = sreg[j] * inv + (d / (float)NTOT) * inv * acc;
        }
        gbar(2 + WARM);
    }
    __syncthreads();

    // ===== phase 5: batch GEMM (f32x2) + relu + rowsum + normalize =====
    const int r0 = bx * 128;

    // load A tile transposed: sAT[k][r] = X[r0+r][k]
    for (int idx = tid; idx < 8192; idx += TPB) {
        int k = idx >> 7, r = idx & 127;
        sAT[k * 128 + r] = X[(size_t)(r0 + r) * 64 + k];
    }

    const int ty = tid >> 4, tx = tid & 15;  // rows ty*8..+7, cols tx*4..+3
    const float sc = d / (float)NTOT;
    float rs[8];
    #pragma unroll
    for (int i = 0; i < 8; i++) rs[i] = 0.0f;
    float vout[8][4];

    __syncthreads();
    for (int cc = 0; cc < 15; cc++) {
        #pragma unroll
        for (int t = 0; t < 4; t++) {
            int f = t * 256 + tid;
            int k = f >> 4, c4 = f & 15;
            ((float4*)sW)[f] = *(const float4*)(g_S + k * NC + cc * 64 + c4 * 4);
        }
        __syncthreads();

        u64 acc[4][4];   // [rowpair p][col c], f32x2 over rows (2p, 2p+1)
        #pragma unroll
        for (int p = 0; p < 4; p++)
            #pragma unroll
            for (int c = 0; c < 4; c++) acc[p][c] = 0ull;

        #pragma unroll 4
        for (int k = 0; k < 64; k++) {
            u64 ap[4];
            #pragma unroll
            for (int p = 0; p < 4; p++)
                ap[p] = *(const u64*)(sAT + k * 128 + ty * 8 + 2 * p);
            float4 b4 = *(const float4*)(sW + k * 64 + tx * 4);
            u64 bd0 = pack_dup(b4.x), bd1 = pack_dup(b4.y);
            u64 bd2 = pack_dup(b4.z), bd3 = pack_dup(b4.w);
            #pragma unroll
            for (int p = 0; p < 4; p++) {
                fma2(acc[p][0], ap[p], bd0);
                fma2(acc[p][1], ap[p], bd1);
                fma2(acc[p][2], ap[p], bd2);
                fma2(acc[p][3], ap[p], bd3);
            }
        }

        // epilogue: base + relu + row-sum; keep chunk 0 for output
        float bb[4];
        #pragma unroll
        for (int c = 0; c < 4; c++) bb[c] = g_base[cc * 64 + tx * 4 + c];
        #pragma unroll
        for (int p = 0; p < 4; p++) {
            #pragma unroll
            for (int c = 0; c < 4; c++) {
                float lo, hi;
                unpack2(acc[p][c], lo, hi);
                float v0 = fmaxf(bb[c] + sc * lo, 0.0f);
                float v1 = fmaxf(bb[c] + sc * hi, 0.0f);
                rs[2 * p]     += v0;
                rs[2 * p + 1] += v1;
                if (cc == 0) { vout[2 * p][c] = v0; vout[2 * p + 1][c] = v1; }
            }
        }
        __syncthreads();
    }

    // row-sum reduction across the 16 column-threads
    #pragma unroll
    for (int i = 0; i < 8; i++) sRS[(ty * 8 + i) * 16 + tx] = rs[i];
    __syncthreads();
    if (tid < 128) {
        float s = 0.0f;
        #pragma unroll
        for (int x = 0; x < 16; x++) s += sRS[tid * 16 + x];
        sInv[tid] = (s > 0.0f) ? 1.0f / s : 1.0f;
    }
    __syncthreads();

    #pragma unroll
    for (int i = 0; i < 8; i++) {
        int row = ty * 8 + i;
        float iv = sInv[row];
        float4 o = make_float4(vout[i][0] * iv, vout[i][1] * iv,
                               vout[i][2] * iv, vout[i][3] * iv);
        *(float4*)(out + (size_t)(r0 + row) * 64 + tx * 4) = o;
    }
}

// ---------------- launch ----------------
extern "C" void kernel_launch(void* const* d_in, const int* in_sizes, int n_in,
                              void* d_out, int out_size) {
    const float* inputs      = (const float*)d_in[0];
    const float* identifiers = (const float*)d_in[1];
    const float* enhancers   = (const float*)d_in[2];
    const float* inhibitors  = (const float*)d_in[3];
    const float* beta        = (const float*)d_in[4];
    const float* delta       = (const float*)d_in[5];
    (void)in_sizes; (void)n_in; (void)out_size;

    cudaFuncSetAttribute(k_fused, cudaFuncAttributeMaxDynamicSharedMemorySize,
                         SMEM_FLOATS * (int)sizeof(float));

    k_init<<<4, 256>>>();
    k_fused<<<GRID, TPB, SMEM_FLOATS * (int)sizeof(float)>>>(
        inputs, identifiers, enhancers, inhibitors, beta, delta, (float*)d_out);
}

// round 4
// speedup vs baseline: 1.5230x; 1.4757x over previous
#include <cuda_runtime.h>
#include <math.h>

#define NTOT 1024
#define NI   64
#define NC   960
#define NR   896        // active warmup rows: global k in [128, 1024)
#define WARM 25
#define FULL 0xffffffffu

// ---------------- device scratch ----------------
__device__ __align__(16) float g_Stop[NI * NC];  // S rows 0..63 (for GEMM), 245KB
__device__ __align__(16) float g_Ep[NR], g_Em[NR], g_Ip[NR], g_Im[NR]; // sorted exp tables
__device__ int   g_pidx_e[NR], g_pidx_i[NR];     // sorted pos -> original k' (0..895)
__device__ int   g_pos_e[NC], g_pos_i[NC];       // per-column split position
__device__ __align__(16) float g_Tp[NC], g_Tm[NC], g_ctop[NC];
__device__ __align__(16) float g_base[NC];

// =================== k_init: tables + Stop ===================
__global__ void k_init(const float* __restrict__ ident, const float* __restrict__ enh,
                       const float* __restrict__ inh,  const float* __restrict__ beta) {
    int b = blockIdx.x, t = threadIdx.x;
    float bb = beta[0];
    if (b < 240) {                                   // Stop: 64 x 960
        int idx = b * 256 + t;
        int k = idx / NC, j = idx - k * NC;
        float id = ident[NI + j];
        g_Stop[idx] = expf(-bb * fabsf(enh[k] - id))
                    - expf(-bb * fabsf(inh[k] - id));
    } else if (b < 248) {                            // ranks + permuted exp tables
        const float* arr = (b < 244) ? enh : inh;
        int k = ((b - ((b < 244) ? 240 : 244)) * 256) + t;
        if (k < NR) {
            float x = arr[128 + k];
            int r = 0;
            for (int k2 = 0; k2 < NR; k2++) {
                float y = arr[128 + k2];
                r += (y < x) || (y == x && k2 < k);
            }
            if (b < 244) { g_pidx_e[r] = k; g_Ep[r] = expf(bb * x); g_Em[r] = expf(-bb * x); }
            else         { g_pidx_i[r] = k; g_Ip[r] = expf(bb * x); g_Im[r] = expf(-bb * x); }
        }
    } else if (b < 256) {                            // split positions per column
        const float* arr = (b < 252) ? enh : inh;
        int j = ((b - ((b < 252) ? 248 : 252)) * 256) + t;
        if (j < NC) {
            float tj = ident[NI + j];
            int c = 0;
            for (int k2 = 0; k2 < NR; k2++) c += (arr[128 + k2] <= tj);
            if (b < 252) g_pos_e[j] = c; else g_pos_i[j] = c;
        }
    } else if (b < 260) {                            // Tp/Tm + top-64 column sums
        int j = (b - 256) * 256 + t;
        if (j < NC) {
            float tj = ident[NI + j];
            g_Tp[j] = expf(bb * tj);
            g_Tm[j] = expf(-bb * tj);
            float c = 0.0f;
            for (int k = 0; k < NI; k++)
                c += expf(-bb * fabsf(enh[k] - tj)) - expf(-bb * fabsf(inh[k] - tj));
            g_ctop[j] = c;
        }
    }
}

// =================== k_warm: 25 iters + base, ONE block ===================
__global__ void __launch_bounds__(1024, 1) k_warm(const float* __restrict__ delta) {
    __shared__ float rA[NC], rB[NC];
    __shared__ float SPe[1024], SQe[1024], SPi[1024], SQi[1024];
    __shared__ float wt[32][4];
    __shared__ float tot1, tot3, s_sh;
    const int t = threadIdx.x, lane = t & 31, warp = t >> 5;

    float Ep = 0, Em = 0, Ip = 0, Im = 0; int pe = 0, pi = 0;
    if (t < NR) { Ep = g_Ep[t]; Em = g_Em[t]; Ip = g_Ip[t]; Im = g_Im[t];
                  // reg index = global_row - 64 = (128 + pidx) - 64 = pidx + 64
                  pe = g_pidx_e[t] + 64; pi = g_pidx_i[t] + 64; }
    float Tp = 0, Tm = 0, ct = 0; int poe = 0, poi = 0;
    if (t < NC) { Tp = g_Tp[t]; Tm = g_Tm[t]; ct = g_ctop[t];
                  poe = g_pos_e[t]; poi = g_pos_i[t];
                  rA[t] = 1.0f / (float)NTOT; }
    float s = 1.0f;
    const float d = delta[0];
    __syncthreads();
    float *rc = rA, *rn = rB;

    for (int it = 0; it <= WARM; it++) {
        float inv = (s > 0.0f) ? 1.0f / s : 1.0f;
        float a0 = 0, a1 = 0, a2 = 0, a3 = 0;
        if (t < NR) {
            float re = rc[pe]; a0 = re * Ep; a1 = re * Em;
            float ri = rc[pi]; a2 = ri * Ip; a3 = ri * Im;
        }
        // warp-level inclusive scans (4 arrays)
        #pragma unroll
        for (int o = 1; o < 32; o <<= 1) {
            float b0 = __shfl_up_sync(FULL, a0, o), b1 = __shfl_up_sync(FULL, a1, o);
            float b2 = __shfl_up_sync(FULL, a2, o), b3 = __shfl_up_sync(FULL, a3, o);
            if (lane >= o) { a0 += b0; a1 += b1; a2 += b2; a3 += b3; }
        }
        if (lane == 31) { wt[warp][0] = a0; wt[warp][1] = a1;
                          wt[warp][2] = a2; wt[warp][3] = a3; }
        __syncthreads();
        if (warp == 0) {                       // scan of 32 warp totals -> exclusive
            float c0 = wt[lane][0], c1 = wt[lane][1], c2 = wt[lane][2], c3 = wt[lane][3];
            float i0 = c0, i1 = c1, i2 = c2, i3 = c3;
            #pragma unroll
            for (int o = 1; o < 32; o <<= 1) {
                float b0 = __shfl_up_sync(FULL, i0, o), b1 = __shfl_up_sync(FULL, i1, o);
                float b2 = __shfl_up_sync(FULL, i2, o), b3 = __shfl_up_sync(FULL, i3, o);
                if (lane >= o) { i0 += b0; i1 += b1; i2 += b2; i3 += b3; }
            }
            wt[lane][0] = i0 - c0; wt[lane][1] = i1 - c1;
            wt[lane][2] = i2 - c2; wt[lane][3] = i3 - c3;
            if (lane == 31) { tot1 = i1; tot3 = i3; }
        }
        __syncthreads();
        SPe[t] = a0 + wt[warp][0]; SQe[t] = a1 + wt[warp][1];
        SPi[t] = a2 + wt[warp][2]; SQi[t] = a3 + wt[warp][3];
        __syncthreads();

        float nv = 0.0f;
        if (t < NC) {
            float spe = poe ? SPe[poe - 1] : 0.0f;
            float sqe = poe ? SQe[poe - 1] : 0.0f;
            float spi = poi ? SPi[poi - 1] : 0.0f;
            float sqi = poi ? SQi[poi - 1] : 0.0f;
            float de  = Tm * spe + Tp * (tot1 - sqe);
            float di  = Tm * spi + Tp * (tot3 - sqi);
            float dot = (de - di) * inv;
            float conc = rc[t] * inv;
            if (it < WARM) {
                float dc = (d / (float)NTOT) * (ct * (1.0f / (float)NTOT) + dot);
                nv = fmaxf(conc + dc, 0.0f);
                rn[t] = nv;
            } else {
                g_base[t] = conc + (d / (float)NTOT) * dot;
            }
        }
        if (it == WARM) break;

        // block reduce s = sum(nv)
        #pragma unroll
        for (int o = 16; o; o >>= 1) nv += __shfl_xor_sync(FULL, nv, o);
        if (lane == 0) wt[warp][0] = nv;
        __syncthreads();
        if (warp == 0) {
            float v = wt[lane][0];
            #pragma unroll
            for (int o = 16; o; o >>= 1) v += __shfl_xor_sync(FULL, v, o);
            if (lane == 0) s_sh = v;
        }
        __syncthreads();
        s = s_sh;
        float* tmp = rc; rc = rn; rn = tmp;
    }
}

// =================== k_gemm: f32x2 batch GEMM + epilogue ===================
typedef unsigned long long u64;
__device__ __forceinline__ u64 pack_dup(float x) {
    u64 r; asm("mov.b64 %0, {%1, %1};" : "=l"(r) : "f"(x)); return r;
}
__device__ __forceinline__ void fma2(u64& dd, u64 a, u64 b) {
    asm("fma.rn.f32x2 %0, %1, %2, %0;" : "+l"(dd) : "l"(a), "l"(b));
}
__device__ __forceinline__ void unpack2(u64 a, float& lo, float& hi) {
    asm("mov.b64 {%0, %1}, %2;" : "=f"(lo), "=f"(hi) : "l"(a));
}

#define SMEM_FLOATS (8192 + 4096 + 2048 + 128)
__global__ void __launch_bounds__(256) k_gemm(const float* __restrict__ X,
                                              const float* __restrict__ delta,
                                              float* __restrict__ out) {
    extern __shared__ float sm[];
    float* sAT  = sm;            // 64 x 128, A transposed k-major
    float* sW   = sm + 8192;     // 64 x 64
    float* sRS  = sm + 12288;    // 128 x 16
    float* sInv = sm + 14336;    // 128
    const int tid = threadIdx.x;
    const int r0  = blockIdx.x * 128;

    for (int idx = tid; idx < 8192; idx += 256) {
        int k = idx >> 7, r = idx & 127;
        sAT[k * 128 + r] = X[(size_t)(r0 + r) * 64 + k];
    }

    const int ty = tid >> 4, tx = tid & 15;
    const float sc = delta[0] / (float)NTOT;
    float rs[8];
    #pragma unroll
    for (int i = 0; i < 8; i++) rs[i] = 0.0f;
    float vout[8][4];

    __syncthreads();
    for (int cc = 0; cc < 15; cc++) {
        #pragma unroll
        for (int q = 0; q < 4; q++) {
            int f = q * 256 + tid;
            int k = f >> 4, c4 = f & 15;
            ((float4*)sW)[f] = *(const float4*)(g_Stop + k * NC + cc * 64 + c4 * 4);
        }
        __syncthreads();

        u64 acc[4][4];
        #pragma unroll
        for (int p = 0; p < 4; p++)
            #pragma unroll
            for (int c = 0; c < 4; c++) acc[p][c] = 0ull;

        #pragma unroll 4
        for (int k = 0; k < 64; k++) {
            u64 ap[4];
            #pragma unroll
            for (int p = 0; p < 4; p++)
                ap[p] = *(const u64*)(sAT + k * 128 + ty * 8 + 2 * p);
            float4 b4 = *(const float4*)(sW + k * 64 + tx * 4);
            u64 bd0 = pack_dup(b4.x), bd1 = pack_dup(b4.y);
            u64 bd2 = pack_dup(b4.z), bd3 = pack_dup(b4.w);
            #pragma unroll
            for (int p = 0; p < 4; p++) {
                fma2(acc[p][0], ap[p], bd0);
                fma2(acc[p][1], ap[p], bd1);
                fma2(acc[p][2], ap[p], bd2);
                fma2(acc[p][3], ap[p], bd3);
            }
        }

        float bb[4];
        #pragma unroll
        for (int c = 0; c < 4; c++) bb[c] = g_base[cc * 64 + tx * 4 + c];
        #pragma unroll
        for (int p = 0; p < 4; p++) {
            #pragma unroll
            for (int c = 0; c < 4; c++) {
                float lo, hi;
                unpack2(acc[p][c], lo, hi);
                float v0 = fmaxf(bb[c] + sc * lo, 0.0f);
                float v1 = fmaxf(bb[c] + sc * hi, 0.0f);
                rs[2 * p]     += v0;
                rs[2 * p + 1] += v1;
                if (cc == 0) { vout[2 * p][c] = v0; vout[2 * p + 1][c] = v1; }
            }
        }
        __syncthreads();
    }

    #pragma unroll
    for (int i = 0; i < 8; i++) sRS[(ty * 8 + i) * 16 + tx] = rs[i];
    __syncthreads();
    if (tid < 128) {
        float s = 0.0f;
        #pragma unroll
        for (int x = 0; x < 16; x++) s += sRS[tid * 16 + x];
        sInv[tid] = (s > 0.0f) ? 1.0f / s : 1.0f;
    }
    __syncthreads();

    #pragma unroll
    for (int i = 0; i < 8; i++) {
        int row = ty * 8 + i;
        float iv = sInv[row];
        float4 o = make_float4(vout[i][0] * iv, vout[i][1] * iv,
                               vout[i][2] * iv, vout[i][3] * iv);
        *(float4*)(out + (size_t)(r0 + row) * 64 + tx * 4) = o;
    }
}

// ---------------- launch ----------------
extern "C" void kernel_launch(void* const* d_in, const int* in_sizes, int n_in,
                              void* d_out, int out_size) {
    const float* inputs      = (const float*)d_in[0];
    const float* identifiers = (const float*)d_in[1];
    const float* enhancers   = (const float*)d_in[2];
    const float* inhibitors  = (const float*)d_in[3];
    const float* beta        = (const float*)d_in[4];
    const float* delta       = (const float*)d_in[5];
    (void)in_sizes; (void)n_in; (void)out_size;

    cudaFuncSetAttribute(k_gemm, cudaFuncAttributeMaxDynamicSharedMemorySize,
                         SMEM_FLOATS * (int)sizeof(float));

    k_init<<<260, 256>>>(identifiers, enhancers, inhibitors, beta);
    k_warm<<<1, 1024>>>(delta);
    k_gemm<<<128, 256, SMEM_FLOATS * (int)sizeof(float)>>>(inputs, delta, (float*)d_out);
}

// round 6
// speedup vs baseline: 2.5135x; 1.6504x over previous
#include <cuda_runtime.h>
#include <cuda_bf16.h>
#include <math.h>
#include <stdint.h>

#define NTOT 1024
#define NI   64
#define NC   960
#define NR   896
#define WARM 25
#define FULL 0xffffffffu

// ---------------- device scratch ----------------
__device__ __align__(16) __nv_bfloat16 g_Bh[NC * 64];  // B[j][k] hi split, row-major (j rows)
__device__ __align__(16) __nv_bfloat16 g_Bl[NC * 64];  // B[j][k] lo split
__device__ __align__(16) float g_Ep[NR], g_Em[NR], g_Ip[NR], g_Im[NR];
__device__ int   g_pidx_e[NR], g_pidx_i[NR];
__device__ int   g_pos_e[NC], g_pos_i[NC];
__device__ __align__(16) float g_Tp[NC], g_Tm[NC], g_ctop[NC];
__device__ __align__(16) float g_base[NC];

__device__ __forceinline__ uint32_t smem_u32(const void* p) {
    uint32_t a;
    asm("{ .reg .u64 t; cvta.to.shared.u64 t, %1; cvt.u32.u64 %0, t; }" : "=r"(a) : "l"(p));
    return a;
}
#define SW128(x) ((x) ^ (((x) >> 3) & 0x70))

#define LDSM_X4(r0, r1, r2, r3, a) \
    asm volatile("ldmatrix.sync.aligned.m8n8.x4.shared.b16 {%0,%1,%2,%3}, [%4];" \
        : "=r"(r0), "=r"(r1), "=r"(r2), "=r"(r3) : "r"(a))

#define MMA16816(d, a, b0, b1) \
    asm volatile("mma.sync.aligned.m16n8k16.row.col.f32.bf16.bf16.f32 " \
        "{%0,%1,%2,%3}, {%4,%5,%6,%7}, {%8,%9}, {%0,%1,%2,%3};" \
        : "+f"((d)[0]), "+f"((d)[1]), "+f"((d)[2]), "+f"((d)[3]) \
        : "r"((a)[0]), "r"((a)[1]), "r"((a)[2]), "r"((a)[3]), "r"(b0), "r"(b1))

// =================== k_init: all tables, warp-parallel ===================
__global__ void k_init(const float* __restrict__ ident, const float* __restrict__ enh,
                       const float* __restrict__ inh,  const float* __restrict__ beta) {
    const int b = blockIdx.x, t = threadIdx.x;
    const int wid = t >> 5, lane = t & 31;
    const float bb = beta[0];

    if (b < 240) {                       // bf16-split B matrix [j][k]
        int idx = b * 256 + t;           // 61440 = 960*64
        int j = idx >> 6, k = idx & 63;
        float id = ident[NI + j];
        float v = expf(-bb * fabsf(enh[k] - id)) - expf(-bb * fabsf(inh[k] - id));
        __nv_bfloat16 h = __float2bfloat16(v);
        __nv_bfloat16 l = __float2bfloat16(v - __bfloat162float(h));
        g_Bh[idx] = h;
        g_Bl[idx] = l;
    } else if (b < 464) {                // ranks + permuted exp tables (warp per elem)
        bool is_e = (b < 352);
        const float* arr = is_e ? enh : inh;
        int k = ((b - (is_e ? 240 : 352)) * 8 + wid);
        float x = arr[128 + k];
        int cnt = 0;
        for (int k2 = lane; k2 < NR; k2 += 32) {
            float y = arr[128 + k2];
            cnt += (y < x) || (y == x && k2 < k);
        }
        #pragma unroll
        for (int o = 16; o; o >>= 1) cnt += __shfl_xor_sync(FULL, cnt, o);
        if (lane == 0) {
            if (is_e) { g_pidx_e[cnt] = k; g_Ep[cnt] = expf(bb * x); g_Em[cnt] = expf(-bb * x); }
            else      { g_pidx_i[cnt] = k; g_Ip[cnt] = expf(bb * x); g_Im[cnt] = expf(-bb * x); }
        }
    } else if (b < 704) {                // split positions (warp per column)
        bool is_e = (b < 584);
        const float* arr = is_e ? enh : inh;
        int j = ((b - (is_e ? 464 : 584)) * 8 + wid);
        float tj = ident[NI + j];
        int cnt = 0;
        for (int k2 = lane; k2 < NR; k2 += 32) cnt += (arr[128 + k2] <= tj);
        #pragma unroll
        for (int o = 16; o; o >>= 1) cnt += __shfl_xor_sync(FULL, cnt, o);
        if (lane == 0) { if (is_e) g_pos_e[j] = cnt; else g_pos_i[j] = cnt; }
    } else if (b < 824) {                // ctop (warp per column)
        int j = (b - 704) * 8 + wid;
        float tj = ident[NI + j];
        float c = 0.0f;
        for (int k = lane; k < NI; k += 32)
            c += expf(-bb * fabsf(enh[k] - tj)) - expf(-bb * fabsf(inh[k] - tj));
        #pragma unroll
        for (int o = 16; o; o >>= 1) c += __shfl_xor_sync(FULL, c, o);
        if (lane == 0) g_ctop[j] = c;
    } else {                             // Tp/Tm
        int j = (b - 824) * 256 + t;
        if (j < NC) {
            float tj = ident[NI + j];
            g_Tp[j] = expf(bb * tj);
            g_Tm[j] = expf(-bb * tj);
        }
    }
}

// =================== k_warm: unchanged (passing) ===================
__global__ void __launch_bounds__(1024, 1) k_warm(const float* __restrict__ delta) {
    __shared__ float rA[NC], rB[NC];
    __shared__ float SPe[1024], SQe[1024], SPi[1024], SQi[1024];
    __shared__ float wt[32][4];
    __shared__ float tot1, tot3, s_sh;
    const int t = threadIdx.x, lane = t & 31, warp = t >> 5;

    float Ep = 0, Em = 0, Ip = 0, Im = 0; int pe = 0, pi = 0;
    if (t < NR) { Ep = g_Ep[t]; Em = g_Em[t]; Ip = g_Ip[t]; Im = g_Im[t];
                  pe = g_pidx_e[t] + 64; pi = g_pidx_i[t] + 64; }
    float Tp = 0, Tm = 0, ct = 0; int poe = 0, poi = 0;
    if (t < NC) { Tp = g_Tp[t]; Tm = g_Tm[t]; ct = g_ctop[t];
                  poe = g_pos_e[t]; poi = g_pos_i[t];
                  rA[t] = 1.0f / (float)NTOT; }
    float s = 1.0f;
    const float d = delta[0];
    __syncthreads();
    float *rc = rA, *rn = rB;

    for (int it = 0; it <= WARM; it++) {
        float inv = (s > 0.0f) ? 1.0f / s : 1.0f;
        float a0 = 0, a1 = 0, a2 = 0, a3 = 0;
        if (t < NR) {
            float re = rc[pe]; a0 = re * Ep; a1 = re * Em;
            float ri = rc[pi]; a2 = ri * Ip; a3 = ri * Im;
        }
        #pragma unroll
        for (int o = 1; o < 32; o <<= 1) {
            float b0 = __shfl_up_sync(FULL, a0, o), b1 = __shfl_up_sync(FULL, a1, o);
            float b2 = __shfl_up_sync(FULL, a2, o), b3 = __shfl_up_sync(FULL, a3, o);
            if (lane >= o) { a0 += b0; a1 += b1; a2 += b2; a3 += b3; }
        }
        if (lane == 31) { wt[warp][0] = a0; wt[warp][1] = a1;
                          wt[warp][2] = a2; wt[warp][3] = a3; }
        __syncthreads();
        if (warp == 0) {
            float c0 = wt[lane][0], c1 = wt[lane][1], c2 = wt[lane][2], c3 = wt[lane][3];
            float i0 = c0, i1 = c1, i2 = c2, i3 = c3;
            #pragma unroll
            for (int o = 1; o < 32; o <<= 1) {
                float b0 = __shfl_up_sync(FULL, i0, o), b1 = __shfl_up_sync(FULL, i1, o);
                float b2 = __shfl_up_sync(FULL, i2, o), b3 = __shfl_up_sync(FULL, i3, o);
                if (lane >= o) { i0 += b0; i1 += b1; i2 += b2; i3 += b3; }
            }
            wt[lane][0] = i0 - c0; wt[lane][1] = i1 - c1;
            wt[lane][2] = i2 - c2; wt[lane][3] = i3 - c3;
            if (lane == 31) { tot1 = i1; tot3 = i3; }
        }
        __syncthreads();
        SPe[t] = a0 + wt[warp][0]; SQe[t] = a1 + wt[warp][1];
        SPi[t] = a2 + wt[warp][2]; SQi[t] = a3 + wt[warp][3];
        __syncthreads();

        float nv = 0.0f;
        if (t < NC) {
            float spe = poe ? SPe[poe - 1] : 0.0f;
            float sqe = poe ? SQe[poe - 1] : 0.0f;
            float spi = poi ? SPi[poi - 1] : 0.0f;
            float sqi = poi ? SQi[poi - 1] : 0.0f;
            float de  = Tm * spe + Tp * (tot1 - sqe);
            float di  = Tm * spi + Tp * (tot3 - sqi);
            float dot = (de - di) * inv;
            float conc = rc[t] * inv;
            if (it < WARM) {
                float dc = (d / (float)NTOT) * (ct * (1.0f / (float)NTOT) + dot);
                nv = fmaxf(conc + dc, 0.0f);
                rn[t] = nv;
            } else {
                g_base[t] = conc + (d / (float)NTOT) * dot;
            }
        }
        if (it == WARM) break;

        #pragma unroll
        for (int o = 16; o; o >>= 1) nv += __shfl_xor_sync(FULL, nv, o);
        if (lane == 0) wt[warp][0] = nv;
        __syncthreads();
        if (warp == 0) {
            float v = wt[lane][0];
            #pragma unroll
            for (int o = 16; o; o >>= 1) v += __shfl_xor_sync(FULL, v, o);
            if (lane == 0) s_sh = v;
        }
        __syncthreads();
        s = s_sh;
        float* tmp = rc; rc = rn; rn = tmp;
    }
}

// =================== k_gemm: mma.sync bf16-split GEMM ===================
// smem byte layout
#define SMA_H  0                 // 128 rows x 128B  (A hi, SW128)
#define SMA_L  16384             // A lo
#define SMB_H  32768             // 64 rows x 128B   (B chunk hi)
#define SMB_L  40960             // B chunk lo
#define SMBASE 49152             // 960 floats
#define SMTOT  (SMBASE + 3840)

__global__ void __launch_bounds__(256)
k_gemm(const float* __restrict__ X, const float* __restrict__ delta,
       float* __restrict__ out) {
    extern __shared__ char sm[];
    const uint32_t sb = smem_u32(sm);
    float* sbase = (float*)(sm + SMBASE);
    const int tid = threadIdx.x, wid = tid >> 5, lane = tid & 31;
    const int gr = lane >> 2, tg = lane & 3;
    const int r0 = blockIdx.x * 128;
    const int m0 = wid * 16;

    for (int i = tid; i < NC; i += 256) sbase[i] = g_base[i];

    // A tile: 128x64 fp32 -> bf16 hi/lo, SW128 swizzled K-major rows (128B)
    for (int i = tid; i < 4096; i += 256) {
        int m = i >> 5, c2 = i & 31;                 // c2 = bf16-pair index
        float2 x = *(const float2*)(X + (size_t)(r0 + m) * 64 + 2 * c2);
        __nv_bfloat162 hp = __floats2bfloat162_rn(x.x, x.y);
        float2 hf = __bfloat1622float2(hp);
        __nv_bfloat162 lp = __floats2bfloat162_rn(x.x - hf.x, x.y - hf.y);
        uint32_t off = SW128((uint32_t)(m * 128 + c2 * 4));
        *(uint32_t*)(sm + SMA_H + off) = *(uint32_t*)&hp;
        *(uint32_t*)(sm + SMA_L + off) = *(uint32_t*)&lp;
    }
    __syncthreads();

    // chunk-invariant A fragments (ldmatrix x4 per k-step, hi and lo)
    // lane -> row m0 + (lane&7) + ((lane>>3)&1)*8 ; 16B-chunk = ks*2 + (lane>>4)
    uint32_t ah[4][4], al[4][4];
    {
        int arow = m0 + (lane & 7) + ((lane >> 3) & 1) * 8;
        int acol = (lane >> 4) & 1;
        #pragma unroll
        for (int ks = 0; ks < 4; ks++) {
            uint32_t off = SW128((uint32_t)(arow * 128 + (ks * 2 + acol) * 16));
            LDSM_X4(ah[ks][0], ah[ks][1], ah[ks][2], ah[ks][3], sb + SMA_H + off);
            LDSM_X4(al[ks][0], al[ks][1], al[ks][2], al[ks][3], sb + SMA_L + off);
        }
    }

    const float sc = delta[0] / (float)NTOT;
    float rsLo = 0.0f, rsHi = 0.0f;
    float2 vlo[8], vhi[8];

    // B ldmatrix lane mapping: row n0 + (lane&7) + ((lane>>4)&1)*8,
    //                          chunk = ks*2 + ((lane>>3)&1)
    const int brow_off = (lane & 7) + ((lane >> 4) & 1) * 8;
    const int bcol_off = (lane >> 3) & 1;

    for (int cc = 0; cc < 15; cc++) {
        // load B chunk (hi+lo) into smem, SW128 swizzled
        #pragma unroll
        for (int q = 0; q < 4; q++) {
            int f = q * 256 + tid;                   // 0..1023 uint4
            int isl = f >> 9;                        // 0: hi, 1: lo
            int r  = (f & 511) >> 3, ch = f & 7;
            const uint4* src = isl ? (const uint4*)g_Bl : (const uint4*)g_Bh;
            uint4 v = src[(size_t)(cc * 64 + r) * 8 + ch];
            uint32_t off = SW128((uint32_t)(r * 128 + ch * 16));
            *(uint4*)(sm + (isl ? SMB_L : SMB_H) + off) = v;
        }
        __syncthreads();

        float dacc[8][4];
        #pragma unroll
        for (int nt = 0; nt < 8; nt++)
            #pragma unroll
            for (int r = 0; r < 4; r++) dacc[nt][r] = 0.0f;

        #pragma unroll
        for (int ks = 0; ks < 4; ks++) {
            #pragma unroll
            for (int np = 0; np < 4; np++) {
                uint32_t boff = SW128((uint32_t)((np * 16 + brow_off) * 128 +
                                                 (ks * 2 + bcol_off) * 16));
                uint32_t b0, b1, b2, b3;
                LDSM_X4(b0, b1, b2, b3, sb + SMB_H + boff);
                MMA16816(dacc[np * 2],     ah[ks], b0, b1);   // Ah*Bh
                MMA16816(dacc[np * 2 + 1], ah[ks], b2, b3);
                MMA16816(dacc[np * 2],     al[ks], b0, b1);   // Al*Bh
                MMA16816(dacc[np * 2 + 1], al[ks], b2, b3);
                LDSM_X4(b0, b1, b2, b3, sb + SMB_L + boff);
                MMA16816(dacc[np * 2],     ah[ks], b0, b1);   // Ah*Bl
                MMA16816(dacc[np * 2 + 1], ah[ks], b2, b3);
            }
        }

        // epilogue: base + relu + row sums (C frag: d0,d1 row gr; d2,d3 row gr+8)
        #pragma unroll
        for (int nt = 0; nt < 8; nt++) {
            float2 bb = *(const float2*)(sbase + cc * 64 + nt * 8 + tg * 2);
            float v00 = fmaxf(bb.x + sc * dacc[nt][0], 0.0f);
            float v01 = fmaxf(bb.y + sc * dacc[nt][1], 0.0f);
            float v10 = fmaxf(bb.x + sc * dacc[nt][2], 0.0f);
            float v11 = fmaxf(bb.y + sc * dacc[nt][3], 0.0f);
            rsLo += v00 + v01;
            rsHi += v10 + v11;
            if (cc == 0) { vlo[nt] = make_float2(v00, v01);
                           vhi[nt] = make_float2(v10, v11); }
        }
        __syncthreads();
    }

    // reduce row sums across the 4 lanes of each row group
    rsLo += __shfl_xor_sync(FULL, rsLo, 1);
    rsLo += __shfl_xor_sync(FULL, rsLo, 2);
    rsHi += __shfl_xor_sync(FULL, rsHi, 1);
    rsHi += __shfl_xor_sync(FULL, rsHi, 2);
    float invLo = (rsLo > 0.0f) ? 1.0f / rsLo : 1.0f;
    float invHi = (rsHi > 0.0f) ? 1.0f / rsHi : 1.0f;

    int rowLo = r0 + m0 + gr, rowHi = rowLo + 8;
    #pragma unroll
    for (int nt = 0; nt < 8; nt++) {
        int c = nt * 8 + tg * 2;
        *(float2*)(out + (size_t)rowLo * 64 + c) =
            make_float2(vlo[nt].x * invLo, vlo[nt].y * invLo);
        *(float2*)(out + (size_t)rowHi * 64 + c) =
            make_float2(vhi[nt].x * invHi, vhi[nt].y * invHi);
    }
}

// ---------------- launch ----------------
extern "C" void kernel_launch(void* const* d_in, const int* in_sizes, int n_in,
                              void* d_out, int out_size) {
    const float* inputs      = (const float*)d_in[0];
    const float* identifiers = (const float*)d_in[1];
    const float* enhancers   = (const float*)d_in[2];
    const float* inhibitors  = (const float*)d_in[3];
    const float* beta        = (const float*)d_in[4];
    const float* delta       = (const float*)d_in[5];
    (void)in_sizes; (void)n_in; (void)out_size;

    cudaFuncSetAttribute(k_gemm, cudaFuncAttributeMaxDynamicSharedMemorySize, SMTOT);

    k_init<<<828, 256>>>(identifiers, enhancers, inhibitors, beta);
    k_warm<<<1, 1024>>>(delta);
    k_gemm<<<128, 256, SMTOT>>>(inputs, delta, (float*)d_out);
}

// round 7
// speedup vs baseline: 2.7439x; 1.0917x over previous
#include <cuda_runtime.h>
#include <cuda_bf16.h>
#include <math.h>
#include <stdint.h>

#define NTOT 1024
#define NI   64
#define NC   960
#define NR   896
#define WARM 25
#define FULL 0xffffffffu

// ---------------- device scratch ----------------
__device__ __align__(16) __nv_bfloat16 g_Bh[NC * 64];
__device__ __align__(16) __nv_bfloat16 g_Bl[NC * 64];
__device__ __align__(16) float g_Ep[NR], g_Em[NR], g_Ip[NR], g_Im[NR];
__device__ __align__(16) int   g_pidx_e[NR], g_pidx_i[NR];
__device__ __align__(16) int   g_pos_e[NC], g_pos_i[NC];
__device__ __align__(16) float g_Tp[NC], g_Tm[NC], g_ctop[NC];
__device__ __align__(16) float g_base[NC];

__device__ __forceinline__ uint32_t smem_u32(const void* p) {
    uint32_t a;
    asm("{ .reg .u64 t; cvta.to.shared.u64 t, %1; cvt.u32.u64 %0, t; }" : "=r"(a) : "l"(p));
    return a;
}
#define SW128(x) ((x) ^ (((x) >> 3) & 0x70))

#define LDSM_X4(r0, r1, r2, r3, a) \
    asm volatile("ldmatrix.sync.aligned.m8n8.x4.shared.b16 {%0,%1,%2,%3}, [%4];" \
        : "=r"(r0), "=r"(r1), "=r"(r2), "=r"(r3) : "r"(a))

#define MMA16816(d, a, b0, b1) \
    asm volatile("mma.sync.aligned.m16n8k16.row.col.f32.bf16.bf16.f32 " \
        "{%0,%1,%2,%3}, {%4,%5,%6,%7}, {%8,%9}, {%0,%1,%2,%3};" \
        : "+f"((d)[0]), "+f"((d)[1]), "+f"((d)[2]), "+f"((d)[3]) \
        : "r"((a)[0]), "r"((a)[1]), "r"((a)[2]), "r"((a)[3]), "r"(b0), "r"(b1))

// =================== k_init: all tables, warp-parallel (unchanged) ==========
__global__ void k_init(const float* __restrict__ ident, const float* __restrict__ enh,
                       const float* __restrict__ inh,  const float* __restrict__ beta) {
    const int b = blockIdx.x, t = threadIdx.x;
    const int wid = t >> 5, lane = t & 31;
    const float bb = beta[0];

    if (b < 240) {
        int idx = b * 256 + t;
        int j = idx >> 6, k = idx & 63;
        float id = ident[NI + j];
        float v = expf(-bb * fabsf(enh[k] - id)) - expf(-bb * fabsf(inh[k] - id));
        __nv_bfloat16 h = __float2bfloat16(v);
        __nv_bfloat16 l = __float2bfloat16(v - __bfloat162float(h));
        g_Bh[idx] = h;
        g_Bl[idx] = l;
    } else if (b < 464) {
        bool is_e = (b < 352);
        const float* arr = is_e ? enh : inh;
        int k = ((b - (is_e ? 240 : 352)) * 8 + wid);
        float x = arr[128 + k];
        int cnt = 0;
        for (int k2 = lane; k2 < NR; k2 += 32) {
            float y = arr[128 + k2];
            cnt += (y < x) || (y == x && k2 < k);
        }
        #pragma unroll
        for (int o = 16; o; o >>= 1) cnt += __shfl_xor_sync(FULL, cnt, o);
        if (lane == 0) {
            if (is_e) { g_pidx_e[cnt] = k; g_Ep[cnt] = expf(bb * x); g_Em[cnt] = expf(-bb * x); }
            else      { g_pidx_i[cnt] = k; g_Ip[cnt] = expf(bb * x); g_Im[cnt] = expf(-bb * x); }
        }
    } else if (b < 704) {
        bool is_e = (b < 584);
        const float* arr = is_e ? enh : inh;
        int j = ((b - (is_e ? 464 : 584)) * 8 + wid);
        float tj = ident[NI + j];
        int cnt = 0;
        for (int k2 = lane; k2 < NR; k2 += 32) cnt += (arr[128 + k2] <= tj);
        #pragma unroll
        for (int o = 16; o; o >>= 1) cnt += __shfl_xor_sync(FULL, cnt, o);
        if (lane == 0) { if (is_e) g_pos_e[j] = cnt; else g_pos_i[j] = cnt; }
    } else if (b < 824) {
        int j = (b - 704) * 8 + wid;
        float tj = ident[NI + j];
        float c = 0.0f;
        for (int k = lane; k < NI; k += 32)
            c += expf(-bb * fabsf(enh[k] - tj)) - expf(-bb * fabsf(inh[k] - tj));
        #pragma unroll
        for (int o = 16; o; o >>= 1) c += __shfl_xor_sync(FULL, c, o);
        if (lane == 0) g_ctop[j] = c;
    } else {
        int j = (b - 824) * 256 + t;
        if (j < NC) {
            float tj = ident[NI + j];
            g_Tp[j] = expf(bb * tj);
            g_Tm[j] = expf(-bb * tj);
        }
    }
}

// =================== k_warm v2: segmented scans ===================
// Scanner threads: t in [0,224) -> e-pair segment t; t in [256,480) -> i-pair.
// Each scanner owns 4 contiguous sorted elements; serial scan + one warp scan.
__global__ void __launch_bounds__(1024, 1) k_warm(const float* __restrict__ delta) {
    __shared__ float rA[NC], rB[NC];
    __shared__ __align__(16) float SPe[NR], SQe[NR], SPi[NR], SQi[NR];
    __shared__ float2 wt2[16];
    __shared__ float wsum[32];
    __shared__ float tot1, tot3, s_sh;
    const int t = threadIdx.x, lane = t & 31, warp = t >> 5;

    const bool role_e = (t < 224);
    const bool role_i = (t >= 256 && t < 480);
    const bool scanner = role_e || role_i;
    const int seg = role_e ? t : (t - 256);
    const int w0  = role_e ? 0 : 8;

    int4 px = make_int4(0, 0, 0, 0);
    float4 Pp = make_float4(0, 0, 0, 0), Pm = Pp;
    if (role_e) {
        px = ((const int4*)g_pidx_e)[seg];
        Pp = ((const float4*)g_Ep)[seg];
        Pm = ((const float4*)g_Em)[seg];
    } else if (role_i) {
        px = ((const int4*)g_pidx_i)[seg];
        Pp = ((const float4*)g_Ip)[seg];
        Pm = ((const float4*)g_Im)[seg];
    }
    px.x += 64; px.y += 64; px.z += 64; px.w += 64;   // reg index = pidx + 64

    float Tp = 0, Tm = 0, ct = 0; int poe = 0, poi = 0;
    if (t < NC) { Tp = g_Tp[t]; Tm = g_Tm[t]; ct = g_ctop[t];
                  poe = g_pos_e[t]; poi = g_pos_i[t];
                  rA[t] = 1.0f / (float)NTOT; }
    float s = 1.0f;
    const float d = delta[0];
    __syncthreads();
    float *rc = rA, *rn = rB;

    for (int it = 0; it <= WARM; it++) {
        float inv = (s > 0.0f) ? 1.0f / s : 1.0f;

        float sP[4], sQ[4], eP = 0, eQ = 0;
        if (scanner) {
            float r0 = rc[px.x], r1 = rc[px.y], r2 = rc[px.z], r3 = rc[px.w];
            sP[0] = r0 * Pp.x;  sQ[0] = r0 * Pm.x;
            sP[1] = sP[0] + r1 * Pp.y;  sQ[1] = sQ[0] + r1 * Pm.y;
            sP[2] = sP[1] + r2 * Pp.z;  sQ[2] = sQ[1] + r2 * Pm.z;
            sP[3] = sP[2] + r3 * Pp.w;  sQ[3] = sQ[2] + r3 * Pm.w;
            float iP = sP[3], iQ = sQ[3];
            #pragma unroll
            for (int o = 1; o < 32; o <<= 1) {
                float bP = __shfl_up_sync(FULL, iP, o);
                float bQ = __shfl_up_sync(FULL, iQ, o);
                if (lane >= o) { iP += bP; iQ += bQ; }
            }
            eP = iP - sP[3];  eQ = iQ - sQ[3];      // warp-exclusive offsets
            if (lane == 31) wt2[warp] = make_float2(iP, iQ);
        }
        __syncthreads();

        if (scanner) {
            int wl = warp - w0;                      // 0..6 within group
            float bP = eP, bQ = eQ;
            #pragma unroll 6
            for (int w = 0; w < wl; w++) { float2 v = wt2[w0 + w]; bP += v.x; bQ += v.y; }
            float* SP = role_e ? SPe : SPi;
            float* SQ = role_e ? SQe : SQi;
            ((float4*)SP)[seg] = make_float4(bP + sP[0], bP + sP[1], bP + sP[2], bP + sP[3]);
            ((float4*)SQ)[seg] = make_float4(bQ + sQ[0], bQ + sQ[1], bQ + sQ[2], bQ + sQ[3]);
        }
        if (t == 0 || t == 256) {
            float tot = 0.0f;
            #pragma unroll
            for (int w = 0; w < 7; w++) tot += wt2[w0 + w].y;
            if (t == 0) tot1 = tot; else tot3 = tot;
        }
        __syncthreads();

        float nv = 0.0f;
        if (t < NC) {
            float spe = poe ? SPe[poe - 1] : 0.0f;
            float sqe = poe ? SQe[poe - 1] : 0.0f;
            float spi = poi ? SPi[poi - 1] : 0.0f;
            float sqi = poi ? SQi[poi - 1] : 0.0f;
            float de  = Tm * spe + Tp * (tot1 - sqe);
            float di  = Tm * spi + Tp * (tot3 - sqi);
            float dot = (de - di) * inv;
            float conc = rc[t] * inv;
            if (it < WARM) {
                float dc = (d / (float)NTOT) * (ct * (1.0f / (float)NTOT) + dot);
                nv = fmaxf(conc + dc, 0.0f);
                rn[t] = nv;
            } else {
                g_base[t] = conc + (d / (float)NTOT) * dot;
            }
        }
        if (it == WARM) break;

        #pragma unroll
        for (int o = 16; o; o >>= 1) nv += __shfl_xor_sync(FULL, nv, o);
        if (lane == 0) wsum[warp] = nv;
        __syncthreads();
        if (warp == 0) {
            float v = wsum[lane];
            #pragma unroll
            for (int o = 16; o; o >>= 1) v += __shfl_xor_sync(FULL, v, o);
            if (lane == 0) s_sh = v;
        }
        __syncthreads();
        s = s_sh;
        float* tmp = rc; rc = rn; rn = tmp;
    }
}

// =================== k_gemm: mma.sync bf16-split GEMM (unchanged) ===========
#define SMA_H  0
#define SMA_L  16384
#define SMB_H  32768
#define SMB_L  40960
#define SMBASE 49152
#define SMTOT  (SMBASE + 3840)

__global__ void __launch_bounds__(256)
k_gemm(const float* __restrict__ X, const float* __restrict__ delta,
       float* __restrict__ out) {
    extern __shared__ char sm[];
    const uint32_t sb = smem_u32(sm);
    float* sbase = (float*)(sm + SMBASE);
    const int tid = threadIdx.x, wid = tid >> 5, lane = tid & 31;
    const int gr = lane >> 2, tg = lane & 3;
    const int r0 = blockIdx.x * 128;
    const int m0 = wid * 16;

    for (int i = tid; i < NC; i += 256) sbase[i] = g_base[i];

    for (int i = tid; i < 4096; i += 256) {
        int m = i >> 5, c2 = i & 31;
        float2 x = *(const float2*)(X + (size_t)(r0 + m) * 64 + 2 * c2);
        __nv_bfloat162 hp = __floats2bfloat162_rn(x.x, x.y);
        float2 hf = __bfloat1622float2(hp);
        __nv_bfloat162 lp = __floats2bfloat162_rn(x.x - hf.x, x.y - hf.y);
        uint32_t off = SW128((uint32_t)(m * 128 + c2 * 4));
        *(uint32_t*)(sm + SMA_H + off) = *(uint32_t*)&hp;
        *(uint32_t*)(sm + SMA_L + off) = *(uint32_t*)&lp;
    }
    __syncthreads();

    uint32_t ah[4][4], al[4][4];
    {
        int arow = m0 + (lane & 7) + ((lane >> 3) & 1) * 8;
        int acol = (lane >> 4) & 1;
        #pragma unroll
        for (int ks = 0; ks < 4; ks++) {
            uint32_t off = SW128((uint32_t)(arow * 128 + (ks * 2 + acol) * 16));
            LDSM_X4(ah[ks][0], ah[ks][1], ah[ks][2], ah[ks][3], sb + SMA_H + off);
            LDSM_X4(al[ks][0], al[ks][1], al[ks][2], al[ks][3], sb + SMA_L + off);
        }
    }

    const float sc = delta[0] / (float)NTOT;
    float rsLo = 0.0f, rsHi = 0.0f;
    float2 vlo[8], vhi[8];

    const int brow_off = (lane & 7) + ((lane >> 4) & 1) * 8;
    const int bcol_off = (lane >> 3) & 1;

    for (int cc = 0; cc < 15; cc++) {
        #pragma unroll
        for (int q = 0; q < 4; q++) {
            int f = q * 256 + tid;
            int isl = f >> 9;
            int r  = (f & 511) >> 3, ch = f & 7;
            const uint4* src = isl ? (const uint4*)g_Bl : (const uint4*)g_Bh;
            uint4 v = src[(size_t)(cc * 64 + r) * 8 + ch];
            uint32_t off = SW128((uint32_t)(r * 128 + ch * 16));
            *(uint4*)(sm + (isl ? SMB_L : SMB_H) + off) = v;
        }
        __syncthreads();

        float dacc[8][4];
        #pragma unroll
        for (int nt = 0; nt < 8; nt++)
            #pragma unroll
            for (int r = 0; r < 4; r++) dacc[nt][r] = 0.0f;

        #pragma unroll
        for (int ks = 0; ks < 4; ks++) {
            #pragma unroll
            for (int np = 0; np < 4; np++) {
                uint32_t boff = SW128((uint32_t)((np * 16 + brow_off) * 128 +
                                                 (ks * 2 + bcol_off) * 16));
                uint32_t b0, b1, b2, b3;
                LDSM_X4(b0, b1, b2, b3, sb + SMB_H + boff);
                MMA16816(dacc[np * 2],     ah[ks], b0, b1);
                MMA16816(dacc[np * 2 + 1], ah[ks], b2, b3);
                MMA16816(dacc[np * 2],     al[ks], b0, b1);
                MMA16816(dacc[np * 2 + 1], al[ks], b2, b3);
                LDSM_X4(b0, b1, b2, b3, sb + SMB_L + boff);
                MMA16816(dacc[np * 2],     ah[ks], b0, b1);
                MMA16816(dacc[np * 2 + 1], ah[ks], b2, b3);
            }
        }

        #pragma unroll
        for (int nt = 0; nt < 8; nt++) {
            float2 bb = *(const float2*)(sbase + cc * 64 + nt * 8 + tg * 2);
            float v00 = fmaxf(bb.x + sc * dacc[nt][0], 0.0f);
            float v01 = fmaxf(bb.y + sc * dacc[nt][1], 0.0f);
            float v10 = fmaxf(bb.x + sc * dacc[nt][2], 0.0f);
            float v11 = fmaxf(bb.y + sc * dacc[nt][3], 0.0f);
            rsLo += v00 + v01;
            rsHi += v10 + v11;
            if (cc == 0) { vlo[nt] = make_float2(v00, v01);
                           vhi[nt] = make_float2(v10, v11); }
        }
        __syncthreads();
    }

    rsLo += __shfl_xor_sync(FULL, rsLo, 1);
    rsLo += __shfl_xor_sync(FULL, rsLo, 2);
    rsHi += __shfl_xor_sync(FULL, rsHi, 1);
    rsHi += __shfl_xor_sync(FULL, rsHi, 2);
    float invLo = (rsLo > 0.0f) ? 1.0f / rsLo : 1.0f;
    float invHi = (rsHi > 0.0f) ? 1.0f / rsHi : 1.0f;

    int rowLo = r0 + m0 + gr, rowHi = rowLo + 8;
    #pragma unroll
    for (int nt = 0; nt < 8; nt++) {
        int c = nt * 8 + tg * 2;
        *(float2*)(out + (size_t)rowLo * 64 + c) =
            make_float2(vlo[nt].x * invLo, vlo[nt].y * invLo);
        *(float2*)(out + (size_t)rowHi * 64 + c) =
            make_float2(vhi[nt].x * invHi, vhi[nt].y * invHi);
    }
}

// ---------------- launch ----------------
extern "C" void kernel_launch(void* const* d_in, const int* in_sizes, int n_in,
                              void* d_out, int out_size) {
    const float* inputs      = (const float*)d_in[0];
    const float* identifiers = (const float*)d_in[1];
    const float* enhancers   = (const float*)d_in[2];
    const float* inhibitors  = (const float*)d_in[3];
    const float* beta        = (const float*)d_in[4];
    const float* delta       = (const float*)d_in[5];
    (void)in_sizes; (void)n_in; (void)out_size;

    cudaFuncSetAttribute(k_gemm, cudaFuncAttributeMaxDynamicSharedMemorySize, SMTOT);

    k_init<<<828, 256>>>(identifiers, enhancers, inhibitors, beta);
    k_warm<<<1, 1024>>>(delta);
    k_gemm<<<128, 256, SMTOT>>>(inputs, delta, (float*)d_out);
}